// round 6
// baseline (speedup 1.0000x reference)
#include <cuda_runtime.h>

// RandFlow: depthwise 41x41 Gaussian (sigma=5) of flow = 2*noise-1, separable.
// R6: scalar FFMA with IMMEDIATE tap multipliers (rt_SMSP=1, no RF-bank cap,
// unlike fma.f32x2 whose 3 distinct reg-pairs hit the bank rule rt=3).
// Pass1: per-channel scalar smem rings (conflict-free LDS.32).
// Pass2: u64 ring (float2), scalar FFMA on both halves.

#define IMG_H 512
#define IMG_W 512
#define IMG_B 16

__device__ unsigned long long g_scratch[IMG_B * IMG_H * IMG_W]; // float2 as u64

__device__ constexpr float GK[41] = {
    0.00033546f, 0.00073182f, 0.00153381f, 0.00308872f, 0.00597603f,
    0.01110900f, 0.01984110f, 0.03404746f, 0.05613476f, 0.08892166f,
    0.13533528f, 0.19789871f, 0.27803730f, 0.37531110f, 0.48675226f,
    0.60653066f, 0.72614904f, 0.83527021f, 0.92311635f, 0.98019867f,
    1.00000000f,
    0.98019867f, 0.92311635f, 0.83527021f, 0.72614904f, 0.60653066f,
    0.48675226f, 0.37531110f, 0.27803730f, 0.19789871f, 0.13533528f,
    0.08892166f, 0.05613476f, 0.03404746f, 0.01984110f, 0.01110900f,
    0.00597603f, 0.00308872f, 0.00153381f, 0.00073182f, 0.00033546f
};

// fold 1/S^2 (S = 12.5326388) and (2x-1) into pass-1 load
#define SCALE_A 0.012733434f
#define SCALE_B (-0.006366717f)

// ---------------- Pass 1: horizontal ---------------------------------------
// 2 rows/block (128 thr), 64 thr/row, 8 px * 2ch per thread.
// smem: per-row, per-channel scalar arrays, skew f(x)=x+(x>>3):
//   lane window base 8t -> 9t words (9 coprime 32) => conflict-free LDS.32.
#define P1W 12
#define SK1 624      // f(551) = 619, padded

__global__ void __launch_bounds__(128) rf_pass1(const float2* __restrict__ in) {
    __shared__ float sx[2][SK1], sy[2][SK1];
    const int half = threadIdx.x >> 6;         // row within block
    const int t    = threadIdx.x & 63;
    const int row  = blockIdx.x * 2 + half;    // b*512 + h
    const float2* src = in + (size_t)row * IMG_W;

    for (int x = t; x < IMG_W + 40; x += 64) {
        float vx = 0.f, vy = 0.f;
        int w = x - 20;
        if ((unsigned)w < (unsigned)IMG_W) {
            float2 v = src[w];
            vx = fmaf(v.x, SCALE_A, SCALE_B);
            vy = fmaf(v.y, SCALE_A, SCALE_B);
        }
        const int f = x + (x >> 3);
        sx[half][f] = vx;
        sy[half][f] = vy;
    }
    __syncthreads();

    const float* Px = sx[half];
    const float* Py = sy[half];
    const int x0 = t * 8;                      // first output pixel

    float wx[P1W], wy[P1W], ax[8], ay[8];
#pragma unroll
    for (int i = 0; i < P1W; ++i) {
        const int x = x0 + i;
        const int f = x + (x >> 3);
        wx[i] = Px[f];
        wy[i] = Py[f];
    }
#pragma unroll
    for (int r = 0; r < 8; ++r) { ax[r] = 0.f; ay[r] = 0.f; }

#pragma unroll
    for (int k = 0; k < 41; ++k) {
#pragma unroll
        for (int r = 0; r < 8; ++r) {
            ax[r] = fmaf(wx[(k + r) % P1W], GK[k], ax[r]);
            ay[r] = fmaf(wy[(k + r) % P1W], GK[k], ay[r]);
        }
        if (k < 37) {                          // prefetch x0 + k + 12 (max 48)
            const int x = x0 + k + P1W;
            const int f = x + (x >> 3);
            wx[k % P1W] = Px[f];
            wy[k % P1W] = Py[f];
        }
    }

    // pack and store 8 float2 = 4x 16B, coalesced (warp covers 2 KB)
    ulonglong2* dst = reinterpret_cast<ulonglong2*>(
        g_scratch + (size_t)row * IMG_W + x0);
#pragma unroll
    for (int j = 0; j < 4; ++j) {
        unsigned long long lo =
            ((unsigned long long)__float_as_uint(ay[2 * j]) << 32) |
             (unsigned long long)__float_as_uint(ax[2 * j]);
        unsigned long long hi =
            ((unsigned long long)__float_as_uint(ay[2 * j + 1]) << 32) |
             (unsigned long long)__float_as_uint(ax[2 * j + 1]);
        dst[j] = make_ulonglong2(lo, hi);
    }
}

// ---------------- Pass 2: vertical -----------------------------------------
// 128 thr = 128 consecutive w; thread: 16 h-outputs * 2 ch (scalar FFMA-imm).
#define W2 24
__global__ void __launch_bounds__(128, 4) rf_pass2(float2* __restrict__ out) {
    const int w  = (blockIdx.x & 3) * 128 + threadIdx.x;
    const int bh = blockIdx.x >> 2;
    const int b  = bh >> 5;
    const int h0 = (bh & 31) * 16;

    const unsigned long long* src =
        g_scratch + (size_t)b * IMG_H * IMG_W + w;

    unsigned long long win[W2];
    float ax[16], ay[16];
#pragma unroll
    for (int i = 0; i < W2; ++i) {
        const int h = h0 + i - 20;
        win[i] = ((unsigned)h < (unsigned)IMG_H) ? src[(size_t)h * IMG_W] : 0ull;
    }
#pragma unroll
    for (int r = 0; r < 16; ++r) { ax[r] = 0.f; ay[r] = 0.f; }

#pragma unroll
    for (int k = 0; k < 41; ++k) {
#pragma unroll
        for (int r = 0; r < 16; ++r) {
            const unsigned long long v = win[(k + r) % W2];
            ax[r] = fmaf(__uint_as_float((unsigned)v),         GK[k], ax[r]);
            ay[r] = fmaf(__uint_as_float((unsigned)(v >> 32)), GK[k], ay[r]);
        }
        if (k < 32) {                          // prefetch i = k + 24
            const int h = h0 + k + 4;
            win[k % W2] = ((unsigned)h < (unsigned)IMG_H) ? src[(size_t)h * IMG_W]
                                                          : 0ull;
        }
    }

    unsigned long long* dst = (unsigned long long*)out
                            + ((size_t)b * IMG_H + h0) * IMG_W + w;
#pragma unroll
    for (int r = 0; r < 16; ++r) {
        dst[(size_t)r * IMG_W] =
            ((unsigned long long)__float_as_uint(ay[r]) << 32) |
             (unsigned long long)__float_as_uint(ax[r]);
    }
}

extern "C" void kernel_launch(void* const* d_in, const int* in_sizes, int n_in,
                              void* d_out, int out_size) {
    const float2* noise = nullptr;
    for (int i = 0; i < n_in; ++i) {
        if (in_sizes[i] == IMG_B * IMG_H * IMG_W * 2) {
            noise = (const float2*)d_in[i];
            break;
        }
    }
    if (!noise) noise = (const float2*)d_in[n_in - 1];

    rf_pass1<<<IMG_B * IMG_H / 2, 128>>>(noise);
    rf_pass2<<<IMG_B * (IMG_H / 16) * (IMG_W / 128), 128>>>((float2*)d_out);
}

// round 7
// speedup vs baseline: 1.2177x; 1.2177x over previous
#include <cuda_runtime.h>

// RandFlow: depthwise 41x41 Gaussian (sigma=5) of flow = 2*noise-1, separable.
// R7 = R5 base (FFMA2, 8 out/thr pass1, 16 out/thr pass2) with pass1 fixes:
//  - coalesced output via smem staging (was 4x wavefront-amplified stores)
//  - float2 STS in fill (no manual u64 packing ALU)

#define IMG_H 512
#define IMG_W 512
#define IMG_B 16

__device__ unsigned long long g_scratch[IMG_B * IMG_H * IMG_W]; // float2 as u64

__device__ constexpr float GK[41] = {
    0.00033546f, 0.00073182f, 0.00153381f, 0.00308872f, 0.00597603f,
    0.01110900f, 0.01984110f, 0.03404746f, 0.05613476f, 0.08892166f,
    0.13533528f, 0.19789871f, 0.27803730f, 0.37531110f, 0.48675226f,
    0.60653066f, 0.72614904f, 0.83527021f, 0.92311635f, 0.98019867f,
    1.00000000f,
    0.98019867f, 0.92311635f, 0.83527021f, 0.72614904f, 0.60653066f,
    0.48675226f, 0.37531110f, 0.27803730f, 0.19789871f, 0.13533528f,
    0.08892166f, 0.05613476f, 0.03404746f, 0.01984110f, 0.01110900f,
    0.00597603f, 0.00308872f, 0.00153381f, 0.00073182f, 0.00033546f
};

// fold 1/S^2 (S = 12.5326388) and (2x-1) into pass-1 load
#define SCALE_A 0.012733434f
#define SCALE_B (-0.006366717f)

__device__ __forceinline__ unsigned long long pk2(float g) {
    unsigned int u = __float_as_uint(g);   // constant-folds for literals
    return ((unsigned long long)u << 32) | (unsigned long long)u;
}
__device__ __forceinline__ void ffma2(unsigned long long& d,
                                      unsigned long long a,
                                      unsigned long long b) {
    asm("fma.rn.f32x2 %0, %1, %2, %0;" : "+l"(d) : "l"(a), "l"(b));
}

// skew: f(x) = x + (x>>3)
#define SKB 624   // f(551)=619, padded

// ---------------- Pass 1: horizontal, 8 out/thread, ring W1=12 -------------
// 64 threads per row, 2 rows per block (128 thr). Grid = 16*512/2 = 4096.
#define W1 12
__global__ void __launch_bounds__(128) rf_pass1(const float2* __restrict__ in) {
    __shared__ unsigned long long s[2][SKB];
    const int half = threadIdx.x >> 6;         // which row in block
    const int t    = threadIdx.x & 63;         // thread within row
    const int row  = blockIdx.x * 2 + half;    // b*512 + h
    const float2* src = in + (size_t)row * IMG_W;
    unsigned long long* S = s[half];

    // fill padded row: x in [0,552), input w = x-20, affine folded.
    // float2 store -> direct STS.64 from the loaded register pair.
    for (int x = t; x < IMG_W + 40; x += 64) {
        float vx = 0.f, vy = 0.f;
        int w = x - 20;
        if ((unsigned)w < (unsigned)IMG_W) {
            float2 v = src[w];
            vx = fmaf(v.x, SCALE_A, SCALE_B);
            vy = fmaf(v.y, SCALE_A, SCALE_B);
        }
        *reinterpret_cast<float2*>(&S[x + (x >> 3)]) = make_float2(vx, vy);
    }
    __syncthreads();

    const int base = t * 9;                    // skewed base (w0 = 8t)
    unsigned long long win[W1], acc[8];
#pragma unroll
    for (int i = 0; i < W1; ++i) win[i] = S[base + i + (i >> 3)];
#pragma unroll
    for (int r = 0; r < 8; ++r) acc[r] = 0ull;

#pragma unroll
    for (int k = 0; k < 41; ++k) {
        const unsigned long long g = pk2(GK[k]);
#pragma unroll
        for (int r = 0; r < 8; ++r) ffma2(acc[r], win[(k + r) % W1], g);
        if (k < 37) {                          // prefetch i = k + 12 (max 48)
            const int i = k + W1;
            win[k % W1] = S[base + i + (i >> 3)];
        }
    }
    __syncthreads();

    // stage outputs at skewed positions f(8t+r) = 9t + r (r<8), then
    // cooperative fully-coalesced stores: x = t + 64j -> 256B segments.
#pragma unroll
    for (int r = 0; r < 8; ++r) S[base + r] = acc[r];
    __syncthreads();

    unsigned long long* dst = g_scratch + (size_t)row * IMG_W;
#pragma unroll
    for (int j = 0; j < 8; ++j) {
        const int x = t + 64 * j;
        dst[x] = S[x + (x >> 3)];
    }
}

// ---------------- Pass 2: vertical, 16 out/thread, ring W2=24 --------------
#define W2 24
__global__ void __launch_bounds__(128, 5) rf_pass2(float2* __restrict__ out) {
    const int w  = (blockIdx.x & 3) * 128 + threadIdx.x;
    const int bh = blockIdx.x >> 2;
    const int b  = bh >> 5;
    const int h0 = (bh & 31) * 16;

    const unsigned long long* src =
        g_scratch + (size_t)b * IMG_H * IMG_W + w;

    unsigned long long win[W2], acc[16];
#pragma unroll
    for (int i = 0; i < W2; ++i) {
        const int h = h0 + i - 20;
        win[i] = ((unsigned)h < (unsigned)IMG_H) ? src[(size_t)h * IMG_W] : 0ull;
    }
#pragma unroll
    for (int r = 0; r < 16; ++r) acc[r] = 0ull;

#pragma unroll
    for (int k = 0; k < 41; ++k) {
        const unsigned long long g = pk2(GK[k]);
#pragma unroll
        for (int r = 0; r < 16; ++r) ffma2(acc[r], win[(k + r) % W2], g);
        if (k < 32) {                          // prefetch i = k + 24
            const int h = h0 + k + 4;
            win[k % W2] = ((unsigned)h < (unsigned)IMG_H) ? src[(size_t)h * IMG_W]
                                                          : 0ull;
        }
    }

    unsigned long long* dst = (unsigned long long*)out
                            + ((size_t)b * IMG_H + h0) * IMG_W + w;
#pragma unroll
    for (int r = 0; r < 16; ++r) dst[(size_t)r * IMG_W] = acc[r];
}

extern "C" void kernel_launch(void* const* d_in, const int* in_sizes, int n_in,
                              void* d_out, int out_size) {
    const float2* noise = nullptr;
    for (int i = 0; i < n_in; ++i) {
        if (in_sizes[i] == IMG_B * IMG_H * IMG_W * 2) {
            noise = (const float2*)d_in[i];
            break;
        }
    }
    if (!noise) noise = (const float2*)d_in[n_in - 1];

    rf_pass1<<<IMG_B * IMG_H / 2, 128>>>(noise);
    rf_pass2<<<IMG_B * (IMG_H / 16) * (IMG_W / 128), 128>>>((float2*)d_out);
}